// round 6
// baseline (speedup 1.0000x reference)
#include <cuda_runtime.h>
#include <cstdint>

#define SLEN   1024
#define BSZ    32
#define HID    1024
#define INDIM  1024
#define M_TOTAL (SLEN * BSZ)   // 32768
#define NFUSED  (2 * HID)      // z and f stacked: 2048

// -------- scratch (__device__ globals: allocation-free rule) --------
__device__ float g_z [(size_t)M_TOTAL * HID];      // z pre-act + bias_z
__device__ float g_f [(size_t)M_TOTAL * HID];      // 0.5*(f pre-act + bias_f)
__device__ float g_af[(size_t)M_TOTAL * INDIM];    // x in mma-fragment order (tf32-rna)
__device__ float g_bf[(size_t)NFUSED * INDIM];     // fused weights in fragment order

__device__ __forceinline__ float rna(float v) {
    uint32_t r;
    asm("cvt.rna.tf32.f32 %0, %1;" : "=r"(r) : "f"(v));
    return __uint_as_float(r);
}

__device__ __forceinline__ void cp16(uint32_t dst, const void* src) {
    asm volatile("cp.async.cg.shared.global [%0], [%1], 16;" :: "r"(dst), "l"(src));
}

// ============ pre-pass: x -> A-fragment order ============
__global__ __launch_bounds__(256)
void prep_a(const float* __restrict__ x, float* __restrict__ Af) {
    size_t u = (size_t)blockIdx.x * 256 + threadIdx.x;      // 0 .. 8388607
    int lane = (int)(u & 31);
    size_t t2 = u >> 5;
    int kt = (int)(t2 & 127);
    int mt = (int)(t2 >> 7);
    int g = lane >> 2, tg = lane & 3;
    size_t m = (size_t)mt * 16 + g;
    int    k = kt * 8 + tg;
    float4 v;
    v.x = rna(x[m * INDIM + k]);
    v.y = rna(x[(m + 8) * INDIM + k]);
    v.z = rna(x[m * INDIM + k + 4]);
    v.w = rna(x[(m + 8) * INDIM + k + 4]);
    ((float4*)Af)[u] = v;
}

// ============ pre-pass: weights -> B-fragment order (fused z|f) ============
__global__ __launch_bounds__(256)
void prep_b(const float* __restrict__ wz, const float* __restrict__ wf,
            float* __restrict__ Bf) {
    size_t u = (size_t)blockIdx.x * 256 + threadIdx.x;      // 0 .. 1048575
    int lane = (int)(u & 31);
    size_t t2 = u >> 5;
    int kt = (int)(t2 & 127);
    int nt = (int)(t2 >> 7);
    int n = nt * 8 + (lane >> 2);
    int k = kt * 8 + (lane & 3);
    const float* w = (n < HID) ? (wz + (size_t)n * INDIM)
                               : (wf + (size_t)(n - HID) * INDIM);
    float2 v;
    v.x = rna(w[k]);
    v.y = rna(w[k + 4]);
    ((float2*)Bf)[u] = v;
}

// ============ tf32 mma.sync GEMM ============
// CTA: 256 thr (8 warps, 2x4), tile 128(M) x 256(fused N), KC=64, 2-stage cp.async
#define BM 128
#define BN 256
#define KC 64
#define NCH (INDIM / KC)          // 16
#define A_STAGE 32768             // 128 rows x 64 k x 4B
#define B_STAGE 65536             // 256 rows x 64 k x 4B
#define STAGE_BYTES (A_STAGE + B_STAGE)   // 98304
#define SMEM_BYTES  (2 * STAGE_BYTES)     // 196608

__device__ __forceinline__ void mma8(float* d, const uint32_t* a, const uint32_t* b) {
    asm volatile(
        "mma.sync.aligned.m16n8k8.row.col.f32.tf32.tf32.f32 "
        "{%0,%1,%2,%3}, {%4,%5,%6,%7}, {%8,%9}, {%0,%1,%2,%3};"
        : "+f"(d[0]), "+f"(d[1]), "+f"(d[2]), "+f"(d[3])
        : "r"(a[0]), "r"(a[1]), "r"(a[2]), "r"(a[3]), "r"(b[0]), "r"(b[1]));
}

__global__ __launch_bounds__(256, 1)
void gemm_tc(const float* __restrict__ Af, const float* __restrict__ Bf,
             const float* __restrict__ bz, const float* __restrict__ bfb) {
    extern __shared__ char smemc[];
    const int tid  = threadIdx.x;
    const int lane = tid & 31;
    const int wid  = tid >> 5;
    const int wm   = wid >> 2;     // 0..1 : 64 M-rows each
    const int wn   = wid & 3;      // 0..3 : 64 N-cols each
    const int mt0  = blockIdx.y * (BM / 16);   // 8 m16-tiles per CTA
    const int nt0  = blockIdx.x * (BN / 8);    // 32 n8-tiles per CTA

    float d[4][8][4];
#pragma unroll
    for (int i = 0; i < 4; i++)
#pragma unroll
        for (int j = 0; j < 8; j++)
#pragma unroll
            for (int q = 0; q < 4; q++) d[i][j][q] = 0.f;

    auto load_chunk = [&](int st, int c) {
        char* stA = smemc + st * STAGE_BYTES;
        char* stB = stA + A_STAGE;
        const int ktg0 = c * 8;
#pragma unroll
        for (int t = 0; t < 8; t++) {                // A: 2048 x 16B
            int idx = tid + t * 256;
            int l = idx & 31, slot = idx >> 5;       // slot = mtl*8 + ktl
            const float* src = Af +
                ((((size_t)(mt0 + (slot >> 3)) * 128) + (ktg0 + (slot & 7))) * 32 + l) * 4;
            cp16((uint32_t)__cvta_generic_to_shared(stA + idx * 16), src);
        }
#pragma unroll
        for (int t = 0; t < 16; t++) {               // B: 4096 x 16B
            int idx = tid + t * 256;
            int pair = idx & 15, slot = idx >> 4;    // slot = ntl*8 + ktl
            const float* src = Bf +
                ((((size_t)(nt0 + (slot >> 3)) * 128) + (ktg0 + (slot & 7))) * 32 + pair * 2) * 2;
            cp16((uint32_t)__cvta_generic_to_shared(stB + idx * 16), src);
        }
        asm volatile("cp.async.commit_group;" ::: "memory");
    };

    uint32_t ab[2][4][4], bb[2][8][2];

    auto load_frags = [&](const float* stAf, const float* stBf, int kt, int pb) {
#pragma unroll
        for (int i = 0; i < 4; i++) {
            float4 v = *(const float4*)(stAf + (((wm * 4 + i) * 8 + kt) * 32 + lane) * 4);
            ab[pb][i][0] = __float_as_uint(v.x); ab[pb][i][1] = __float_as_uint(v.y);
            ab[pb][i][2] = __float_as_uint(v.z); ab[pb][i][3] = __float_as_uint(v.w);
        }
#pragma unroll
        for (int j = 0; j < 8; j++) {
            float2 v = *(const float2*)(stBf + (((wn * 8 + j) * 8 + kt) * 32 + lane) * 2);
            bb[pb][j][0] = __float_as_uint(v.x); bb[pb][j][1] = __float_as_uint(v.y);
        }
    };

    load_chunk(0, 0);

    for (int c = 0; c < NCH; ++c) {
        const int st = c & 1;
        if (c + 1 < NCH) {
            load_chunk(st ^ 1, c + 1);               // overlap DMA with compute of c
            asm volatile("cp.async.wait_group 1;" ::: "memory");
        } else {
            asm volatile("cp.async.wait_group 0;" ::: "memory");
        }
        __syncthreads();

        const float* stAf = (const float*)(smemc + st * STAGE_BYTES);
        const float* stBf = (const float*)(smemc + st * STAGE_BYTES + A_STAGE);

        load_frags(stAf, stBf, 0, 0);
#pragma unroll
        for (int kt = 0; kt < 8; kt++) {
            const int pb = kt & 1;
            if (kt < 7) load_frags(stAf, stBf, kt + 1, pb ^ 1);
#pragma unroll
            for (int i = 0; i < 4; i++)
#pragma unroll
                for (int j = 0; j < 8; j++) mma8(d[i][j], ab[pb][i], bb[pb][j]);
        }
        __syncthreads();    // all warps done with stage st before it is overwritten
    }

    // ---- epilogue: +bias, 0.5x for f-half, store to g_z / g_f ----
    const int g  = lane >> 2, tg = lane & 3;
    const int n0f = nt0 * 8;                     // fused col base (multiple of 256)
    const bool isF = (n0f >= HID);
    float*       outp  = isF ? g_f : g_z;
    const float* bp    = isF ? bfb : bz;
    const float  scale = isF ? 0.5f : 1.0f;
    const int colBase  = (n0f - (isF ? HID : 0)) + wn * 64;

#pragma unroll
    for (int j = 0; j < 8; j++) {
        const int col = colBase + j * 8 + 2 * tg;
        const float2 bbv = *(const float2*)(bp + col);
#pragma unroll
        for (int i = 0; i < 4; i++) {
            const size_t row = (size_t)blockIdx.y * BM + wm * 64 + i * 16 + g;
            float2 v0, v1;
            v0.x = scale * (d[i][j][0] + bbv.x);
            v0.y = scale * (d[i][j][1] + bbv.y);
            v1.x = scale * (d[i][j][2] + bbv.x);
            v1.y = scale * (d[i][j][3] + bbv.y);
            *(float2*)(outp + row * HID + col)       = v0;
            *(float2*)(outp + (row + 8) * HID + col) = v1;
        }
    }
}

// ============ sequential scan: cp.async deep stream ============
// 4 channels per thread, 32 threads/block, 32-stage smem ring (32KB).
// Each thread streams only its own 16B/array per stage -> no __syncthreads.
#define PF 32

__device__ __forceinline__ float tanh_fast(float v) {
    float r;
    asm("tanh.approx.f32 %0, %1;" : "=f"(r) : "f"(v));
    return r;
}

__global__ __launch_bounds__(32)
void scan_kernel(const float* __restrict__ state,
                 const float* __restrict__ wvz, const float* __restrict__ wvf,
                 float* __restrict__ out) {
    __shared__ float4 buf[PF][32][2];   // [stage][thread][0=z,1=f]  = 32KB
    const int t = threadIdx.x;
    const int C = (blockIdx.x * 32 + t) * 4;      // channel base
    const int h0 = C & (HID - 1);

    float cell[4], wz[4], wfh[4];
#pragma unroll
    for (int c = 0; c < 4; c++) {
        cell[c] = state[C + c];
        wz[c]   = wvz[h0 + c];
        wfh[c]  = 0.5f * wvf[h0 + c];
    }

    const float* zsrc = g_z + C;
    const float* fsrc = g_f + C;

    // prologue: fill the ring
#pragma unroll 4
    for (int s = 0; s < PF; s++) {
        cp16((uint32_t)__cvta_generic_to_shared(&buf[s][t][0]), zsrc + (size_t)s * M_TOTAL);
        cp16((uint32_t)__cvta_generic_to_shared(&buf[s][t][1]), fsrc + (size_t)s * M_TOTAL);
        asm volatile("cp.async.commit_group;" ::: "memory");
    }

#pragma unroll 1
    for (int s = 0; s < SLEN; s++) {
        asm volatile("cp.async.wait_group %0;" :: "n"(PF - 1) : "memory");
        const int slot = s & (PF - 1);
        float4 z4 = buf[slot][t][0];
        float4 f4 = buf[slot][t][1];
        // refill this slot (reads above already executed)
        if (s + PF < SLEN) {
            cp16((uint32_t)__cvta_generic_to_shared(&buf[slot][t][0]),
                 zsrc + (size_t)(s + PF) * M_TOTAL);
            cp16((uint32_t)__cvta_generic_to_shared(&buf[slot][t][1]),
                 fsrc + (size_t)(s + PF) * M_TOTAL);
        }
        asm volatile("cp.async.commit_group;" ::: "memory");

        float zv[4] = {z4.x, z4.y, z4.z, z4.w};
        float fv[4] = {f4.x, f4.y, f4.z, f4.w};
        float4 o;
        float* ov = (float*)&o;
#pragma unroll
        for (int c = 0; c < 4; c++) {
            float zpart = tanh_fast(fmaf(wz[c],  cell[c], zv[c]));
            float tt    = tanh_fast(fmaf(wfh[c], cell[c], fv[c]));
            float fpart = fmaf(0.5f, tt, 0.5f);
            cell[c] = fmaf(fpart, cell[c] - zpart, zpart);
            ov[c] = cell[c];
        }
        *(float4*)(out + (size_t)s * M_TOTAL + C) = o;
    }
}

// ============ launch ============
extern "C" void kernel_launch(void* const* d_in, const int* in_sizes, int n_in,
                              void* d_out, int out_size) {
    const float* x      = (const float*)d_in[0];
    const float* state  = (const float*)d_in[1];
    const float* wm_z   = (const float*)d_in[2];
    const float* wm_f   = (const float*)d_in[3];
    const float* wv_z   = (const float*)d_in[4];
    const float* wv_f   = (const float*)d_in[5];
    const float* bias_z = (const float*)d_in[6];
    const float* bias_f = (const float*)d_in[7];
    float* out = (float*)d_out;

    float *af, *bf;
    cudaGetSymbolAddress((void**)&af, g_af);
    cudaGetSymbolAddress((void**)&bf, g_bf);

    cudaFuncSetAttribute(gemm_tc, cudaFuncAttributeMaxDynamicSharedMemorySize, SMEM_BYTES);

    prep_a<<<32768, 256>>>(x, af);
    prep_b<<<4096, 256>>>(wm_z, wm_f, bf);

    dim3 grid(NFUSED / BN, M_TOTAL / BM);   // (8, 256)
    gemm_tc<<<grid, 256, SMEM_BYTES>>>(af, bf, bias_z, bias_f);

    scan_kernel<<<M_TOTAL / 128, 32>>>(state, wv_z, wv_f, out);
}